// round 13
// baseline (speedup 1.0000x reference)
#include <cuda_runtime.h>
#include <cuda_fp16.h>
#include <math.h>

// Problem constants
#define BB   16
#define CC   256
#define OO   256
#define HH   32
#define WW   32
#define EE   4
#define CR   16
#define GG   8
#define CPG  32
#define HWSZ 1024
#define EPSV 1e-5f

#define PADW 34
#define PADPX (PADW * PADW)
#define KTOT (CC * 9)              // 2304
#define NSTG 4
#define TILE_A 16384               // 128 px-rows x 128B (K=64 fp16)
#define TILE_B 32768               // 256 o-rows  x 128B
#define STAGE_BYTES (TILE_A + TILE_B)
#define SMEM_TOTAL (NSTG * STAGE_BYTES)   // 196608

// ---------------- scratch ----------------------------------------------------
__device__ float  g_pooled[BB * CC];
__device__ float  g_gate[BB * EE];
__device__ int    g_actlist[BB * EE];
__device__ int    g_nact;
__device__ __half g_xT[(size_t)BB * PADPX * CC];             // padded px-major fp16
__device__ __half g_wT[(size_t)EE * 9 * OO * CC];            // [e][rs][o][c] fp16
__device__ __half g_swT[OO * CC];                            // shared 1x1 weights fp16
__device__ __half g_shared_raw[(size_t)BB * OO * HWSZ];      // fp16 raw conv outputs
__device__ __half g_expert_raw[(size_t)BB * EE * OO * HWSZ]; // fp16 raw conv outputs
// deterministic GN partials: [slot 0..79][group 0..7][warp_m 0..3][px_tile 0..7]
#define NSLOT (BB + BB * EE)                                  // 80
__device__ float  g_psum[NSLOT * GG * 4 * 8];
__device__ float  g_psq [NSLOT * GG * 4 * 8];
__device__ float  g_sh_mean[BB * GG], g_sh_rstd[BB * GG];
__device__ float  g_ex_mean[BB * EE * GG], g_ex_rstd[BB * EE * GG];

// ---------------- helpers ----------------------------------------------------
__device__ __forceinline__ float warpsum(float v) {
    #pragma unroll
    for (int o = 16; o > 0; o >>= 1) v += __shfl_down_sync(0xffffffffu, v, o);
    return v;
}
__device__ __forceinline__ float silu(float v) { return v / (1.0f + expf(-v)); }

__device__ __forceinline__ unsigned smem_u32(const void* p) {
    unsigned a;
    asm("{ .reg .u64 t; cvta.to.shared.u64 t, %1; cvt.u32.u64 %0, t; }" : "=r"(a) : "l"(p));
    return a;
}
__device__ __forceinline__ void cp16(unsigned dst, const void* src) {
    asm volatile("cp.async.cg.shared.global [%0], [%1], 16;" :: "r"(dst), "l"(src));
}
__device__ __forceinline__ void cp_commit() { asm volatile("cp.async.commit_group;"); }

__device__ __forceinline__ void ldm4(unsigned& r0, unsigned& r1, unsigned& r2, unsigned& r3,
                                     unsigned addr) {
    asm volatile("ldmatrix.sync.aligned.m8n8.x4.shared.b16 {%0,%1,%2,%3}, [%4];"
                 : "=r"(r0), "=r"(r1), "=r"(r2), "=r"(r3) : "r"(addr));
}

__device__ __forceinline__ void mma_f16(float* c, unsigned a0, unsigned a1, unsigned a2, unsigned a3,
                                        unsigned b0, unsigned b1) {
    asm volatile(
        "mma.sync.aligned.m16n8k16.row.col.f32.f16.f16.f32 "
        "{%0,%1,%2,%3}, {%4,%5,%6,%7}, {%8,%9}, {%0,%1,%2,%3};"
        : "+f"(c[0]), "+f"(c[1]), "+f"(c[2]), "+f"(c[3])
        : "r"(a0), "r"(a1), "r"(a2), "r"(a3), "r"(b0), "r"(b1));
}

// ---------------- K1: router (+ active list) -----------------------------------
__global__ void router_kernel(const float* __restrict__ w1, const float* __restrict__ b1,
                              const float* __restrict__ w2, const float* __restrict__ b2) {
    __shared__ float hs[BB][CR];
    __shared__ float lg[BB][EE];
    int tid = threadIdx.x;
    {
        int b = tid / CR, j = tid % CR;
        float s = b1[j];
        const float* wr = w1 + j * CC;
        const float* pr = g_pooled + b * CC;
        for (int c = 0; c < CC; c++) s = fmaf(wr[c], pr[c], s);
        hs[b][j] = silu(s);
    }
    __syncthreads();
    if (tid < BB * EE) {
        int b = tid / EE, e = tid % EE;
        float s = b2[e];
        for (int j = 0; j < CR; j++) s = fmaf(w2[e * CR + j], hs[b][j], s);
        lg[b][e] = s;
    }
    __syncthreads();
    if (tid < BB) {
        int b = tid;
        float m = lg[b][0];
        for (int e = 1; e < EE; e++) m = fmaxf(m, lg[b][e]);
        float p[EE]; float Z = 0.f;
        for (int e = 0; e < EE; e++) { p[e] = expf(lg[b][e] - m); Z += p[e]; }
        for (int e = 0; e < EE; e++) p[e] /= Z;
        int i1 = 0;
        for (int e = 1; e < EE; e++) if (p[e] > p[i1]) i1 = e;
        int i2 = -1;
        for (int e = 0; e < EE; e++) {
            if (e == i1) continue;
            if (i2 < 0 || p[e] > p[i2]) i2 = e;
        }
        float v1 = p[i1], v2 = p[i2], sum = v1 + v2;
        float wA = v1 / sum, wB = v2 / sum;
        if (wA < 0.01f) wA = 0.f;
        if (wB < 0.01f) wB = 0.f;
        for (int e = 0; e < EE; e++) g_gate[b * EE + e] = 0.f;
        g_gate[b * EE + i1] = wA;
        g_gate[b * EE + i2] = wB;
    }
    __syncthreads();
    if (tid == 0) {
        int n = 0;
        for (int be = 0; be < BB * EE; be++)
            if (g_gate[be] != 0.f) g_actlist[n++] = be;
        g_nact = n;
    }
}

// ---------------- K0: fused prep (xt + wrepack + swt + pool), fp16 -------------
__global__ void prep_kernel(const float* __restrict__ x, const float* __restrict__ ew,
                            const float* __restrict__ sw) {
    int bid = blockIdx.x;
    int tid = threadIdx.x;
    if (bid < 544) {
        int b = bid / 34;
        int hp = bid % 34;
        int h = hp - 1;
        __half* outrow = g_xT + ((size_t)b * PADPX + (size_t)hp * PADW) * CC;
        const __half hz = __float2half_rn(0.f);
        if (h < 0 || h >= HH) {
            for (int i = tid; i < PADW * CC; i += 256) outrow[i] = hz;
            return;
        }
        outrow[tid] = hz;
        outrow[33 * CC + tid] = hz;
        __shared__ float s[CC][33];
        for (int i = tid; i < CC * WW; i += 256) {
            int c = i >> 5, w = i & 31;
            s[c][w] = x[((size_t)(b * CC + c)) * HWSZ + h * WW + w];
        }
        __syncthreads();
        for (int i = tid; i < WW * CC; i += 256) {
            int w = i >> 8, c = i & 255;
            outrow[(size_t)(w + 1) * CC + c] = __float2half_rn(s[c][w]);
        }
    } else if (bid < 1568) {
        int idx = (bid - 544) * 256 + tid;          // e*65536 + o*256 + c
        int c = idx & 255, o = (idx >> 8) & 255, e = idx >> 16;
        const float* src = ew + (size_t)idx * 9;
        #pragma unroll
        for (int j = 0; j < 9; j++)
            g_wT[(((size_t)(e * 9 + j) * OO + o) << 8) + c] = __float2half_rn(src[j]);
    } else if (bid < 1824) {
        int idx = (bid - 1568) * 256 + tid;         // o*256 + c
        int c = idx & 255, o = idx >> 8;
        g_swT[(o << 8) + c] = __float2half_rn(sw[idx]);
    } else {
        int warp = tid >> 5, lane = tid & 31;
        int idx = (bid - 1824) * 8 + warp;          // b*CC + c
        const float* p = x + (size_t)idx * HWSZ;
        float s = 0.f;
        for (int i = lane; i < HWSZ; i += 32) s += p[i];
        s = warpsum(s);
        if (lane == 0) g_pooled[idx] = s * (1.0f / HWSZ);
    }
}

// ---------------- K2: fp16 warp-MMA GEMM, 1024 threads (8 warps/SMSP) ----------
// grid (8 px-tiles, 48): y<32 EXPERT (long CTAs first) via g_actlist, y>=32 shared.
// CTA tile 128px x 256o; warp grid 4(M) x 8(N); warp tile 32x32 (m16n8k16).
__global__ void __launch_bounds__(1024, 1)
gemm_kernel() {
    extern __shared__ char smem[];
    unsigned sb = smem_u32(smem);
    int tid = threadIdx.x, warp = tid >> 5, lane = tid & 31;
    int warp_m = warp >> 3, warp_n = warp & 7;
    int g = lane >> 2, q = lane & 3;

    int zz = blockIdx.y;
    bool is_shared = (zz >= BB * EE / 2);           // y>=32 -> shared
    int b, e = 0, slot;
    if (is_shared) { b = zz - BB * EE / 2; slot = b; }
    else {
        if (zz >= g_nact) return;
        int be = g_actlist[zz];
        b = be >> 2; e = be & 3; slot = BB + be;
    }
    int p0 = blockIdx.x * 128;
    const int NITER = is_shared ? (CC / 64) : (KTOT / 64);   // 4 or 36 (both even)

    // -------- load-stage addressing ------------------------------------------
    int arow = tid >> 3, aq = tid & 7;
    int p = p0 + arow;
    int ppad = ((p >> 5) + 1) * PADW + (p & 31) + 1;
    const __half* aSrcBase = g_xT + ((size_t)b * PADPX + ppad) * CC + aq * 8;
    int brow = tid >> 2, bh = tid & 3;
    const __half* bSrcBase = is_shared
        ? g_swT + ((size_t)brow << 8) + bh * 16
        : g_wT + ((size_t)(e * 9) * OO + brow) * CC + bh * 16;
    unsigned xrA = (unsigned)(arow & 7) << 4;
    unsigned xrB = (unsigned)(brow & 7) << 4;
    unsigned aDstRow = sb + arow * 128;
    unsigned bDstRow = sb + TILE_A + brow * 128;
    unsigned aq16 = (unsigned)aq * 16, bh32 = (unsigned)bh * 32;

    auto load_stage = [&](int iter, int buf) {
        int c0, droff;
        long long boff;
        if (is_shared) { c0 = iter << 6; droff = 0; boff = c0; }
        else {
            int rs = iter >> 2; c0 = (iter & 3) << 6;
            droff = (rs / 3 - 1) * PADW + (rs % 3 - 1);
            boff = (long long)rs * OO * CC + c0;
        }
        const __half* as = aSrcBase + (long long)droff * CC + c0;
        const __half* bs = bSrcBase + boff;
        unsigned aDst = aDstRow + buf * STAGE_BYTES;
        unsigned bDst = bDstRow + buf * STAGE_BYTES;
        cp16(aDst + (aq16 ^ xrA), as);
        cp16(bDst + ((bh32)      ^ xrB), bs);
        cp16(bDst + ((bh32 + 16) ^ xrB), bs + 8);
        cp_commit();
    };

    // -------- ldmatrix fragment addressing ------------------------------------
    unsigned l7 = lane & 7;
    unsigned key = l7 << 4;
    unsigned rsel = (((unsigned)lane >> 3) & 1u) * 8u;
    unsigned hsel = ((unsigned)lane >> 4) << 4;               // 0 or 16
    unsigned rowA = (unsigned)(warp_m * 32) + l7 + rsel;
    unsigned aOff = rowA * 128u;
    unsigned rowB = (unsigned)(warp_n * 32) + l7 + rsel;
    unsigned bOff = TILE_A + rowB * 128u;

    // 4-way phase stagger across warps (reads only; deterministic per thread)
    unsigned kphase = (unsigned)warp & 3u;

    float acc[2][4][4] = {};

    auto compute = [&](int buf) {
        unsigned base = sb + buf * STAGE_BYTES;
        #pragma unroll
        for (int ks0 = 0; ks0 < 4; ks0++) {
            unsigned kstep = ((unsigned)ks0 + kphase) & 3u;
            unsigned kb = ((kstep * 32u) + hsel) ^ key;
            unsigned a[2][4];
            #pragma unroll
            for (int mi = 0; mi < 2; mi++)
                ldm4(a[mi][0], a[mi][1], a[mi][2], a[mi][3],
                     base + aOff + mi * 2048u + kb);
            unsigned bf[2][4];
            #pragma unroll
            for (int j = 0; j < 2; j++)
                ldm4(bf[j][0], bf[j][1], bf[j][2], bf[j][3],
                     base + bOff + j * 2048u + kb);
            #pragma unroll
            for (int mi = 0; mi < 2; mi++) {
                #pragma unroll
                for (int j = 0; j < 2; j++) {
                    mma_f16(acc[mi][2 * j],     a[mi][0], a[mi][1], a[mi][2], a[mi][3],
                            bf[j][0], bf[j][2]);
                    mma_f16(acc[mi][2 * j + 1], a[mi][0], a[mi][1], a[mi][2], a[mi][3],
                            bf[j][1], bf[j][3]);
                }
            }
        }
    };

    // -------- pipeline: one barrier per TWO iterations -------------------------
    load_stage(0, 0);
    load_stage(1, 1);
    for (int i = 0; i < NITER; i += 2) {
        asm volatile("cp.async.wait_group 0;" ::: "memory");
        __syncthreads();
        if (i + 2 < NITER) load_stage(i + 2, (i + 2) & 3);
        if (i + 3 < NITER) load_stage(i + 3, (i + 3) & 3);
        compute(i & 3);
        compute((i + 1) & 3);
    }

    // -------- fused GroupNorm partials (deterministic, no atomics) -------------
    {
        float s = 0.f, sq = 0.f;
        #pragma unroll
        for (int mi = 0; mi < 2; mi++)
            #pragma unroll
            for (int ni = 0; ni < 4; ni++)
                #pragma unroll
                for (int c = 0; c < 4; c++) {
                    float v = acc[mi][ni][c];
                    s += v;
                    sq = fmaf(v, v, sq);
                }
        s = warpsum(s); sq = warpsum(sq);
        if (lane == 0) {
            int idx = ((slot * GG + warp_n) * 4 + warp_m) * 8 + blockIdx.x;
            g_psum[idx] = s;
            g_psq[idx]  = sq;
        }
    }
    __syncthreads();   // all compute done before smem reuse

    // -------- epilogue: transpose through smem, fp16 coalesced stores ----------
    float* T = (float*)smem;                      // 256 o-rows x stride 132
    #pragma unroll
    for (int mi = 0; mi < 2; mi++) {
        int m = warp_m * 32 + mi * 16 + g;
        #pragma unroll
        for (int ni = 0; ni < 4; ni++) {
            int n = warp_n * 32 + ni * 8 + 2 * q;
            T[n * 132 + m]           = acc[mi][ni][0];
            T[(n + 1) * 132 + m]     = acc[mi][ni][1];
            T[n * 132 + m + 8]       = acc[mi][ni][2];
            T[(n + 1) * 132 + m + 8] = acc[mi][ni][3];
        }
    }
    __syncthreads();

    __half* outp = is_shared ? g_shared_raw + (size_t)b * OO * HWSZ
                             : g_expert_raw + ((size_t)(b * EE + e)) * OO * HWSZ;
    #pragma unroll
    for (int rr = 0; rr < 8; rr++) {
        int n = warp * 8 + rr;
        float4 v = *(const float4*)(T + n * 132 + lane * 4);
        __half2 h01 = __floats2half2_rn(v.x, v.y);
        __half2 h23 = __floats2half2_rn(v.z, v.w);
        uint2 u;
        u.x = *(unsigned*)&h01;
        u.y = *(unsigned*)&h23;
        *(uint2*)(outp + (size_t)n * HWSZ + p0 + lane * 4) = u;
    }
}

// ---------------- K3: GroupNorm finalize (single block) ------------------------
__global__ void finalize_kernel() {
    int i = threadIdx.x;                           // 0..639
    if (i >= (BB + BB * EE) * GG) return;
    int slot = i / GG, g = i % GG;                 // slot 0..79
    float S = 0.f, Q = 0.f;
    int base = (slot * GG + g) * 32;
    #pragma unroll
    for (int j = 0; j < 32; j++) { S += g_psum[base + j]; Q += g_psq[base + j]; }
    const float inv = 1.0f / (CPG * HWSZ);
    float mean = S * inv;
    float var = Q * inv - mean * mean;
    float rstd = rsqrtf(var + EPSV);
    if (slot < BB) { g_sh_mean[slot * GG + g] = mean; g_sh_rstd[slot * GG + g] = rstd; }
    else {
        int be = slot - BB;
        g_ex_mean[be * GG + g] = mean; g_ex_rstd[be * GG + g] = rstd;
    }
}

// ---------------- K4: normalize + SiLU + gated combine (half4 loads) -----------
__global__ void combine_kernel(const float* __restrict__ egam, const float* __restrict__ ebet,
                               const float* __restrict__ sgam, const float* __restrict__ sbet,
                               float* __restrict__ out) {
    size_t i4 = (size_t)blockIdx.x * 256 + threadIdx.x;   // over BB*OO*HWSZ/4
    size_t t = i4 >> 8;                                    // 256 half4 per (b,o)
    int o = (int)(t & 255);
    int b = (int)(t >> 8);
    int g = o >> 5;

    uint2 vv = ((const uint2*)g_shared_raw)[i4];
    __half2 v01 = *(__half2*)&vv.x, v23 = *(__half2*)&vv.y;
    float2 f01 = __half22float2(v01), f23 = __half22float2(v23);
    float m = g_sh_mean[b * GG + g], r = g_sh_rstd[b * GG + g];
    float ga = sgam[o], be_ = sbet[o];
    float4 res;
    res.x = silu(fmaf((f01.x - m) * r, ga, be_));
    res.y = silu(fmaf((f01.y - m) * r, ga, be_));
    res.z = silu(fmaf((f23.x - m) * r, ga, be_));
    res.w = silu(fmaf((f23.y - m) * r, ga, be_));

    #pragma unroll
    for (int e = 0; e < EE; e++) {
        float ge = g_gate[b * EE + e];
        if (ge != 0.f) {
            int beg = b * EE + e;
            size_t ei = ((size_t)beg * OO + o) * (HWSZ / 4) + (i4 & 255);
            uint2 ew2 = ((const uint2*)g_expert_raw)[ei];
            __half2 e01 = *(__half2*)&ew2.x, e23 = *(__half2*)&ew2.y;
            float2 g01 = __half22float2(e01), g23 = __half22float2(e23);
            float em = g_ex_mean[beg * GG + g], er = g_ex_rstd[beg * GG + g];
            float eg = egam[e * OO + o], eb = ebet[e * OO + o];
            res.x = fmaf(ge, silu(fmaf((g01.x - em) * er, eg, eb)), res.x);
            res.y = fmaf(ge, silu(fmaf((g01.y - em) * er, eg, eb)), res.y);
            res.z = fmaf(ge, silu(fmaf((g23.x - em) * er, eg, eb)), res.z);
            res.w = fmaf(ge, silu(fmaf((g23.y - em) * er, eg, eb)), res.w);
        }
    }
    ((float4*)out)[i4] = res;
}

// ---------------- launch ------------------------------------------------------
extern "C" void kernel_launch(void* const* d_in, const int* in_sizes, int n_in,
                              void* d_out, int out_size) {
    const float* x    = (const float*)d_in[0];
    const float* rw1  = (const float*)d_in[1];
    const float* rb1  = (const float*)d_in[2];
    const float* rw2  = (const float*)d_in[3];
    const float* rb2  = (const float*)d_in[4];
    const float* ew   = (const float*)d_in[5];
    const float* egam = (const float*)d_in[6];
    const float* ebet = (const float*)d_in[7];
    const float* sw   = (const float*)d_in[8];
    const float* sgam = (const float*)d_in[9];
    const float* sbet = (const float*)d_in[10];
    float* out = (float*)d_out;

    cudaFuncSetAttribute(gemm_kernel, cudaFuncAttributeMaxDynamicSharedMemorySize, SMEM_TOTAL);

    prep_kernel<<<2336, 256>>>(x, ew, sw);
    router_kernel<<<1, 256>>>(rw1, rb1, rw2, rb2);
    gemm_kernel<<<dim3(8, BB + BB * EE / 2), 1024, SMEM_TOTAL>>>();
    finalize_kernel<<<1, 640>>>();
    combine_kernel<<<(BB * OO * HWSZ / 4) / 256, 256>>>(egam, ebet, sgam, sbet, out);
}

// round 14
// speedup vs baseline: 1.1138x; 1.1138x over previous
#include <cuda_runtime.h>
#include <cuda_fp16.h>
#include <math.h>

// Problem constants
#define BB   16
#define CC   256
#define OO   256
#define HH   32
#define WW   32
#define EE   4
#define CR   16
#define GG   8
#define CPG  32
#define HWSZ 1024
#define EPSV 1e-5f

#define PADW 34
#define PADPX (PADW * PADW)
#define KTOT (CC * 9)              // 2304
#define NSTG 4
#define TILE_A 16384               // 128 px-rows x 128B (K=64 fp16)
#define TILE_B 32768               // 256 o-rows  x 128B
#define STAGE_BYTES (TILE_A + TILE_B)
#define SMEM_TOTAL (NSTG * STAGE_BYTES)   // 196608

// ---------------- scratch ----------------------------------------------------
__device__ float  g_pooled[BB * CC];
__device__ float  g_gate[BB * EE];
__device__ int    g_actlist[BB * EE];
__device__ int    g_nact;
__device__ __half g_xT[(size_t)BB * PADPX * CC];             // padded px-major fp16
__device__ __half g_wT[(size_t)EE * 9 * OO * CC];            // [e][rs][o][c] fp16
__device__ __half g_swT[OO * CC];                            // shared 1x1 weights fp16
__device__ __half g_shared_raw[(size_t)BB * OO * HWSZ];      // fp16 raw conv outputs
__device__ __half g_expert_raw[(size_t)BB * EE * OO * HWSZ]; // fp16 raw conv outputs
// deterministic GN partials: [slot 0..79][group 0..7][warp_m 0..3][px_tile 0..7]
#define NSLOT (BB + BB * EE)                                  // 80
__device__ float  g_psum[NSLOT * GG * 4 * 8];
__device__ float  g_psq [NSLOT * GG * 4 * 8];
__device__ float  g_sh_mean[BB * GG], g_sh_rstd[BB * GG];
__device__ float  g_ex_mean[BB * EE * GG], g_ex_rstd[BB * EE * GG];

// ---------------- helpers ----------------------------------------------------
__device__ __forceinline__ float warpsum(float v) {
    #pragma unroll
    for (int o = 16; o > 0; o >>= 1) v += __shfl_down_sync(0xffffffffu, v, o);
    return v;
}
__device__ __forceinline__ float silu(float v) { return v / (1.0f + expf(-v)); }

__device__ __forceinline__ unsigned smem_u32(const void* p) {
    unsigned a;
    asm("{ .reg .u64 t; cvta.to.shared.u64 t, %1; cvt.u32.u64 %0, t; }" : "=r"(a) : "l"(p));
    return a;
}
__device__ __forceinline__ void cp16(unsigned dst, const void* src) {
    asm volatile("cp.async.cg.shared.global [%0], [%1], 16;" :: "r"(dst), "l"(src));
}
__device__ __forceinline__ void cp_commit() { asm volatile("cp.async.commit_group;"); }

__device__ __forceinline__ void ldm4(unsigned& r0, unsigned& r1, unsigned& r2, unsigned& r3,
                                     unsigned addr) {
    asm volatile("ldmatrix.sync.aligned.m8n8.x4.shared.b16 {%0,%1,%2,%3}, [%4];"
                 : "=r"(r0), "=r"(r1), "=r"(r2), "=r"(r3) : "r"(addr));
}

__device__ __forceinline__ void mma_f16(float* c, unsigned a0, unsigned a1, unsigned a2, unsigned a3,
                                        unsigned b0, unsigned b1) {
    asm volatile(
        "mma.sync.aligned.m16n8k16.row.col.f32.f16.f16.f32 "
        "{%0,%1,%2,%3}, {%4,%5,%6,%7}, {%8,%9}, {%0,%1,%2,%3};"
        : "+f"(c[0]), "+f"(c[1]), "+f"(c[2]), "+f"(c[3])
        : "r"(a0), "r"(a1), "r"(a2), "r"(a3), "r"(b0), "r"(b1));
}

// ---------------- K1: router (+ active list) -----------------------------------
__global__ void router_kernel(const float* __restrict__ w1, const float* __restrict__ b1,
                              const float* __restrict__ w2, const float* __restrict__ b2) {
    __shared__ float hs[BB][CR];
    __shared__ float lg[BB][EE];
    int tid = threadIdx.x;
    {
        int b = tid / CR, j = tid % CR;
        float s = b1[j];
        const float* wr = w1 + j * CC;
        const float* pr = g_pooled + b * CC;
        for (int c = 0; c < CC; c++) s = fmaf(wr[c], pr[c], s);
        hs[b][j] = silu(s);
    }
    __syncthreads();
    if (tid < BB * EE) {
        int b = tid / EE, e = tid % EE;
        float s = b2[e];
        for (int j = 0; j < CR; j++) s = fmaf(w2[e * CR + j], hs[b][j], s);
        lg[b][e] = s;
    }
    __syncthreads();
    if (tid < BB) {
        int b = tid;
        float m = lg[b][0];
        for (int e = 1; e < EE; e++) m = fmaxf(m, lg[b][e]);
        float p[EE]; float Z = 0.f;
        for (int e = 0; e < EE; e++) { p[e] = expf(lg[b][e] - m); Z += p[e]; }
        for (int e = 0; e < EE; e++) p[e] /= Z;
        int i1 = 0;
        for (int e = 1; e < EE; e++) if (p[e] > p[i1]) i1 = e;
        int i2 = -1;
        for (int e = 0; e < EE; e++) {
            if (e == i1) continue;
            if (i2 < 0 || p[e] > p[i2]) i2 = e;
        }
        float v1 = p[i1], v2 = p[i2], sum = v1 + v2;
        float wA = v1 / sum, wB = v2 / sum;
        if (wA < 0.01f) wA = 0.f;
        if (wB < 0.01f) wB = 0.f;
        for (int e = 0; e < EE; e++) g_gate[b * EE + e] = 0.f;
        g_gate[b * EE + i1] = wA;
        g_gate[b * EE + i2] = wB;
    }
    __syncthreads();
    if (tid == 0) {
        int n = 0;
        for (int be = 0; be < BB * EE; be++)
            if (g_gate[be] != 0.f) g_actlist[n++] = be;
        g_nact = n;
    }
}

// ---------------- K0: fused prep (xt + wrepack + swt + pool), fp16 -------------
__global__ void prep_kernel(const float* __restrict__ x, const float* __restrict__ ew,
                            const float* __restrict__ sw) {
    int bid = blockIdx.x;
    int tid = threadIdx.x;
    if (bid < 544) {
        int b = bid / 34;
        int hp = bid % 34;
        int h = hp - 1;
        __half* outrow = g_xT + ((size_t)b * PADPX + (size_t)hp * PADW) * CC;
        const __half hz = __float2half_rn(0.f);
        if (h < 0 || h >= HH) {
            for (int i = tid; i < PADW * CC; i += 256) outrow[i] = hz;
            return;
        }
        outrow[tid] = hz;
        outrow[33 * CC + tid] = hz;
        __shared__ float s[CC][33];
        for (int i = tid; i < CC * WW; i += 256) {
            int c = i >> 5, w = i & 31;
            s[c][w] = x[((size_t)(b * CC + c)) * HWSZ + h * WW + w];
        }
        __syncthreads();
        for (int i = tid; i < WW * CC; i += 256) {
            int w = i >> 8, c = i & 255;
            outrow[(size_t)(w + 1) * CC + c] = __float2half_rn(s[c][w]);
        }
    } else if (bid < 1568) {
        int idx = (bid - 544) * 256 + tid;          // e*65536 + o*256 + c
        int c = idx & 255, o = (idx >> 8) & 255, e = idx >> 16;
        const float* src = ew + (size_t)idx * 9;
        #pragma unroll
        for (int j = 0; j < 9; j++)
            g_wT[(((size_t)(e * 9 + j) * OO + o) << 8) + c] = __float2half_rn(src[j]);
    } else if (bid < 1824) {
        int idx = (bid - 1568) * 256 + tid;         // o*256 + c
        int c = idx & 255, o = idx >> 8;
        g_swT[(o << 8) + c] = __float2half_rn(sw[idx]);
    } else {
        int warp = tid >> 5, lane = tid & 31;
        int idx = (bid - 1824) * 8 + warp;          // b*CC + c
        const float* p = x + (size_t)idx * HWSZ;
        float s = 0.f;
        for (int i = lane; i < HWSZ; i += 32) s += p[i];
        s = warpsum(s);
        if (lane == 0) g_pooled[idx] = s * (1.0f / HWSZ);
    }
}

// ---------------- K2: fp16 warp-MMA GEMM, 1024 threads (8 warps/SMSP) ----------
// grid (8 px-tiles, 48): y<32 EXPERT (long CTAs first) via g_actlist, y>=32 shared.
// CTA tile 128px x 256o; warp grid 4(M) x 8(N); warp tile 32x32 (m16n8k16).
__global__ void __launch_bounds__(1024, 1)
gemm_kernel() {
    extern __shared__ char smem[];
    unsigned sb = smem_u32(smem);
    int tid = threadIdx.x, warp = tid >> 5, lane = tid & 31;
    int warp_m = warp >> 3, warp_n = warp & 7;
    int g = lane >> 2, q = lane & 3;

    int zz = blockIdx.y;
    bool is_shared = (zz >= BB * EE / 2);           // y>=32 -> shared
    int b, e = 0, slot;
    if (is_shared) { b = zz - BB * EE / 2; slot = b; }
    else {
        if (zz >= g_nact) return;
        int be = g_actlist[zz];
        b = be >> 2; e = be & 3; slot = BB + be;
    }
    int p0 = blockIdx.x * 128;
    const int NITER = is_shared ? (CC / 64) : (KTOT / 64);   // 4 or 36 (both even)

    // -------- load-stage addressing ------------------------------------------
    int arow = tid >> 3, aq = tid & 7;
    int p = p0 + arow;
    int ppad = ((p >> 5) + 1) * PADW + (p & 31) + 1;
    const __half* aSrcBase = g_xT + ((size_t)b * PADPX + ppad) * CC + aq * 8;
    int brow = tid >> 2, bh = tid & 3;
    const __half* bSrcBase = is_shared
        ? g_swT + ((size_t)brow << 8) + bh * 16
        : g_wT + ((size_t)(e * 9) * OO + brow) * CC + bh * 16;
    unsigned xrA = (unsigned)(arow & 7) << 4;
    unsigned xrB = (unsigned)(brow & 7) << 4;
    unsigned aDstRow = sb + arow * 128;
    unsigned bDstRow = sb + TILE_A + brow * 128;
    unsigned aq16 = (unsigned)aq * 16, bh32 = (unsigned)bh * 32;

    auto load_stage = [&](int iter, int buf) {
        int c0, droff;
        long long boff;
        if (is_shared) { c0 = iter << 6; droff = 0; boff = c0; }
        else {
            int rs = iter >> 2; c0 = (iter & 3) << 6;
            droff = (rs / 3 - 1) * PADW + (rs % 3 - 1);
            boff = (long long)rs * OO * CC + c0;
        }
        const __half* as = aSrcBase + (long long)droff * CC + c0;
        const __half* bs = bSrcBase + boff;
        unsigned aDst = aDstRow + buf * STAGE_BYTES;
        unsigned bDst = bDstRow + buf * STAGE_BYTES;
        cp16(aDst + (aq16 ^ xrA), as);
        cp16(bDst + ((bh32)      ^ xrB), bs);
        cp16(bDst + ((bh32 + 16) ^ xrB), bs + 8);
        cp_commit();
    };

    // -------- ldmatrix fragment addressing ------------------------------------
    unsigned l7 = lane & 7;
    unsigned key = l7 << 4;
    unsigned rsel = (((unsigned)lane >> 3) & 1u) * 8u;
    unsigned hsel = ((unsigned)lane >> 4) << 4;               // 0 or 16
    unsigned rowA = (unsigned)(warp_m * 32) + l7 + rsel;
    unsigned aOff = rowA * 128u;
    unsigned rowB = (unsigned)(warp_n * 32) + l7 + rsel;
    unsigned bOff = TILE_A + rowB * 128u;

    // 4-way phase stagger across warps (reads only; deterministic per thread)
    unsigned kphase = (unsigned)warp & 3u;

    float acc[2][4][4] = {};

    auto compute = [&](int buf) {
        unsigned base = sb + buf * STAGE_BYTES;
        #pragma unroll
        for (int ks0 = 0; ks0 < 4; ks0++) {
            unsigned kstep = ((unsigned)ks0 + kphase) & 3u;
            unsigned kb = ((kstep * 32u) + hsel) ^ key;
            unsigned a[2][4];
            #pragma unroll
            for (int mi = 0; mi < 2; mi++)
                ldm4(a[mi][0], a[mi][1], a[mi][2], a[mi][3],
                     base + aOff + mi * 2048u + kb);
            unsigned bf[2][4];
            #pragma unroll
            for (int j = 0; j < 2; j++)
                ldm4(bf[j][0], bf[j][1], bf[j][2], bf[j][3],
                     base + bOff + j * 2048u + kb);
            #pragma unroll
            for (int mi = 0; mi < 2; mi++) {
                #pragma unroll
                for (int j = 0; j < 2; j++) {
                    mma_f16(acc[mi][2 * j],     a[mi][0], a[mi][1], a[mi][2], a[mi][3],
                            bf[j][0], bf[j][2]);
                    mma_f16(acc[mi][2 * j + 1], a[mi][0], a[mi][1], a[mi][2], a[mi][3],
                            bf[j][1], bf[j][3]);
                }
            }
        }
    };

    // -------- pipeline: one barrier per TWO iterations -------------------------
    load_stage(0, 0);
    load_stage(1, 1);
    for (int i = 0; i < NITER; i += 2) {
        asm volatile("cp.async.wait_group 0;" ::: "memory");
        __syncthreads();
        if (i + 2 < NITER) load_stage(i + 2, (i + 2) & 3);
        if (i + 3 < NITER) load_stage(i + 3, (i + 3) & 3);
        compute(i & 3);
        compute((i + 1) & 3);
    }

    // -------- fused GroupNorm partials (deterministic, no atomics) -------------
    {
        float s = 0.f, sq = 0.f;
        #pragma unroll
        for (int mi = 0; mi < 2; mi++)
            #pragma unroll
            for (int ni = 0; ni < 4; ni++)
                #pragma unroll
                for (int c = 0; c < 4; c++) {
                    float v = acc[mi][ni][c];
                    s += v;
                    sq = fmaf(v, v, sq);
                }
        s = warpsum(s); sq = warpsum(sq);
        if (lane == 0) {
            int idx = ((slot * GG + warp_n) * 4 + warp_m) * 8 + blockIdx.x;
            g_psum[idx] = s;
            g_psq[idx]  = sq;
        }
    }
    __syncthreads();   // all compute done before smem reuse

    // -------- epilogue: transpose through smem, fp16 coalesced stores ----------
    float* T = (float*)smem;                      // 256 o-rows x stride 132
    #pragma unroll
    for (int mi = 0; mi < 2; mi++) {
        int m = warp_m * 32 + mi * 16 + g;
        #pragma unroll
        for (int ni = 0; ni < 4; ni++) {
            int n = warp_n * 32 + ni * 8 + 2 * q;
            T[n * 132 + m]           = acc[mi][ni][0];
            T[(n + 1) * 132 + m]     = acc[mi][ni][1];
            T[n * 132 + m + 8]       = acc[mi][ni][2];
            T[(n + 1) * 132 + m + 8] = acc[mi][ni][3];
        }
    }
    __syncthreads();

    __half* outp = is_shared ? g_shared_raw + (size_t)b * OO * HWSZ
                             : g_expert_raw + ((size_t)(b * EE + e)) * OO * HWSZ;
    #pragma unroll
    for (int rr = 0; rr < 8; rr++) {
        int n = warp * 8 + rr;
        float4 v = *(const float4*)(T + n * 132 + lane * 4);
        __half2 h01 = __floats2half2_rn(v.x, v.y);
        __half2 h23 = __floats2half2_rn(v.z, v.w);
        uint2 u;
        u.x = *(unsigned*)&h01;
        u.y = *(unsigned*)&h23;
        *(uint2*)(outp + (size_t)n * HWSZ + p0 + lane * 4) = u;
    }
}

// ---------------- K3: GroupNorm finalize (one warp per item) -------------------
// 640 items x 32 partial-pairs; lane j reads partial j, warp-reduce, lane 0 writes.
__global__ void finalize_kernel() {
    int warp = threadIdx.x >> 5, lane = threadIdx.x & 31;
    int item = blockIdx.x * 32 + warp;             // 0..639
    if (item >= (BB + BB * EE) * GG) return;
    int slot = item / GG, g = item % GG;
    int base = (slot * GG + g) * 32;
    float S = warpsum(g_psum[base + lane]);
    float Q = warpsum(g_psq[base + lane]);
    if (lane == 0) {
        const float inv = 1.0f / (CPG * HWSZ);
        float mean = S * inv;
        float var = Q * inv - mean * mean;
        float rstd = rsqrtf(var + EPSV);
        if (slot < BB) { g_sh_mean[slot * GG + g] = mean; g_sh_rstd[slot * GG + g] = rstd; }
        else {
            int be = slot - BB;
            g_ex_mean[be * GG + g] = mean; g_ex_rstd[be * GG + g] = rstd;
        }
    }
}

// ---------------- K4: normalize + SiLU + gated combine (half4 loads) -----------
__global__ void combine_kernel(const float* __restrict__ egam, const float* __restrict__ ebet,
                               const float* __restrict__ sgam, const float* __restrict__ sbet,
                               float* __restrict__ out) {
    size_t i4 = (size_t)blockIdx.x * 256 + threadIdx.x;   // over BB*OO*HWSZ/4
    size_t t = i4 >> 8;                                    // 256 half4 per (b,o)
    int o = (int)(t & 255);
    int b = (int)(t >> 8);
    int g = o >> 5;

    uint2 vv = ((const uint2*)g_shared_raw)[i4];
    __half2 v01 = *(__half2*)&vv.x, v23 = *(__half2*)&vv.y;
    float2 f01 = __half22float2(v01), f23 = __half22float2(v23);
    float m = g_sh_mean[b * GG + g], r = g_sh_rstd[b * GG + g];
    float ga = sgam[o], be_ = sbet[o];
    float4 res;
    res.x = silu(fmaf((f01.x - m) * r, ga, be_));
    res.y = silu(fmaf((f01.y - m) * r, ga, be_));
    res.z = silu(fmaf((f23.x - m) * r, ga, be_));
    res.w = silu(fmaf((f23.y - m) * r, ga, be_));

    #pragma unroll
    for (int e = 0; e < EE; e++) {
        float ge = g_gate[b * EE + e];
        if (ge != 0.f) {
            int beg = b * EE + e;
            size_t ei = ((size_t)beg * OO + o) * (HWSZ / 4) + (i4 & 255);
            uint2 ew2 = ((const uint2*)g_expert_raw)[ei];
            __half2 e01 = *(__half2*)&ew2.x, e23 = *(__half2*)&ew2.y;
            float2 g01 = __half22float2(e01), g23 = __half22float2(e23);
            float em = g_ex_mean[beg * GG + g], er = g_ex_rstd[beg * GG + g];
            float eg = egam[e * OO + o], eb = ebet[e * OO + o];
            res.x = fmaf(ge, silu(fmaf((g01.x - em) * er, eg, eb)), res.x);
            res.y = fmaf(ge, silu(fmaf((g01.y - em) * er, eg, eb)), res.y);
            res.z = fmaf(ge, silu(fmaf((g23.x - em) * er, eg, eb)), res.z);
            res.w = fmaf(ge, silu(fmaf((g23.y - em) * er, eg, eb)), res.w);
        }
    }
    ((float4*)out)[i4] = res;
}

// ---------------- launch ------------------------------------------------------
extern "C" void kernel_launch(void* const* d_in, const int* in_sizes, int n_in,
                              void* d_out, int out_size) {
    const float* x    = (const float*)d_in[0];
    const float* rw1  = (const float*)d_in[1];
    const float* rb1  = (const float*)d_in[2];
    const float* rw2  = (const float*)d_in[3];
    const float* rb2  = (const float*)d_in[4];
    const float* ew   = (const float*)d_in[5];
    const float* egam = (const float*)d_in[6];
    const float* ebet = (const float*)d_in[7];
    const float* sw   = (const float*)d_in[8];
    const float* sgam = (const float*)d_in[9];
    const float* sbet = (const float*)d_in[10];
    float* out = (float*)d_out;

    cudaFuncSetAttribute(gemm_kernel, cudaFuncAttributeMaxDynamicSharedMemorySize, SMEM_TOTAL);

    prep_kernel<<<2336, 256>>>(x, ew, sw);
    router_kernel<<<1, 256>>>(rw1, rb1, rw2, rb2);
    gemm_kernel<<<dim3(8, BB + BB * EE / 2), 1024, SMEM_TOTAL>>>();
    finalize_kernel<<<20, 1024>>>();
    combine_kernel<<<(BB * OO * HWSZ / 4) / 256, 256>>>(egam, ebet, sgam, sbet, out);
}